// round 4
// baseline (speedup 1.0000x reference)
#include <cuda_runtime.h>
#include <cuda_fp16.h>
#include <cstdint>

// ---------------------------------------------------------------------------
// GCN layer on GB300 (sm_103a), 5-kernel pipeline:
//  K1 gemm+hist : h = xW + b (FFMA2 row-pair GEMM, fp16 h) + histogram whose
//                 atomicAdd return value IS the edge's rank within its row
//  K2 scanB     : per-256-block exclusive scan (shuffle-based), reset counts
//  K3 scanP     : single-block exclusive scan of partials (shuffle-based)
//  K4 scatter   : pure permute (no atomics): pairs[base+rank] = (col,val)
//  K5 gather    : warp-per-row SpMM gather (1 L2 line / edge) + fused PReLU
// ---------------------------------------------------------------------------

#define IN_FT   128
#define OUT_FT  64
#define N_CAP   131072
#define E_CAP   1605632
#define NB_CAP  512

typedef unsigned long long u64;

static __device__ __half          g_h[(size_t)N_CAP * OUT_FT];  // 16.8 MB
static __device__ int            g_cnt[N_CAP + 2];   // zero at entry
static __device__ int            g_lex[N_CAP + 2];   // block-local excl scan
static __device__ int            g_part[NB_CAP];     // block sums -> excl scan
static __device__ unsigned short g_rank[E_CAP];      // edge rank within row
static __device__ int2           g_pairs[E_CAP];     // CSR (col, val bits)

// ---- packed fp32x2 helpers -------------------------------------------------
__device__ __forceinline__ u64 pack2(float lo, float hi) {
    u64 r;
    asm("mov.b64 %0, {%1, %2};" : "=l"(r) : "f"(lo), "f"(hi));
    return r;
}
__device__ __forceinline__ float2 unpack2(u64 v) {
    float2 r;
    asm("mov.b64 {%0, %1}, %2;" : "=f"(r.x), "=f"(r.y) : "l"(v));
    return r;
}
__device__ __forceinline__ u64 fma2(u64 a, u64 b, u64 c) {
    u64 d;
    asm("fma.rn.f32x2 %0, %1, %2, %3;" : "=l"(d) : "l"(a), "l"(b), "l"(c));
    return d;
}

// ---------------------------------------------------------------------------
// K1: GEMM (64-row tile, 128 threads) + fused histogram-with-rank.
// Xs transposed: Xs[k*64 + row]. Thread = 4 row-pairs (8 rows) x 4 cols.
// ---------------------------------------------------------------------------
__global__ __launch_bounds__(128)
void gemm_hist_kernel(const float* __restrict__ x,
                      const float* __restrict__ W,
                      const float* __restrict__ b,
                      const int*   __restrict__ erow,
                      int N, int E) {
    __shared__ float Xs[IN_FT * 64];   // 32 KB, [k][row]

    const int tid  = threadIdx.x;
    const int row0 = blockIdx.x * 64;

    {
        const int r    = tid & 63;
        const int grow = row0 + r;
        const int c4b  = (tid >> 6) * 16;
        const bool ok  = (grow < N);
        const float4* xr = reinterpret_cast<const float4*>(x + (size_t)grow * IN_FT);
        #pragma unroll
        for (int p = 0; p < 16; p++) {
            const int c4 = c4b + p;
            float4 v = make_float4(0.f, 0.f, 0.f, 0.f);
            if (ok) v = xr[c4];
            Xs[(c4 * 4 + 0) * 64 + r] = v.x;
            Xs[(c4 * 4 + 1) * 64 + r] = v.y;
            Xs[(c4 * 4 + 2) * 64 + r] = v.z;
            Xs[(c4 * 4 + 3) * 64 + r] = v.w;
        }
    }
    __syncthreads();

    const int tx = tid & 15;   // cols [4*tx, 4*tx+4)
    const int ty = tid >> 4;   // rows [ty*8, ty*8+8) as 4 pairs

    u64 acc[4][4];
    #pragma unroll
    for (int i = 0; i < 4; i++)
        #pragma unroll
        for (int j = 0; j < 4; j++) acc[i][j] = 0ULL;

    const float4* __restrict__ Wg = reinterpret_cast<const float4*>(W);

    #pragma unroll 4
    for (int k = 0; k < IN_FT; k++) {
        const float4 w = __ldg(&Wg[k * 16 + tx]);
        u64 wd[4];
        wd[0] = pack2(w.x, w.x);
        wd[1] = pack2(w.y, w.y);
        wd[2] = pack2(w.z, w.z);
        wd[3] = pack2(w.w, w.w);

        const u64* xr = reinterpret_cast<const u64*>(&Xs[k * 64 + ty * 8]);
        u64 xp[4];
        xp[0] = xr[0]; xp[1] = xr[1]; xp[2] = xr[2]; xp[3] = xr[3];

        #pragma unroll
        for (int i = 0; i < 4; i++)
            #pragma unroll
            for (int j = 0; j < 4; j++)
                acc[i][j] = fma2(xp[i], wd[j], acc[i][j]);
    }

    // Epilogue: unpack row pairs, add bias, convert fp16, store 8B per row.
    const float4 bv = __ldg(reinterpret_cast<const float4*>(b) + tx);
    #pragma unroll
    for (int i = 0; i < 4; i++) {
        const float2 c0 = unpack2(acc[i][0]);
        const float2 c1 = unpack2(acc[i][1]);
        const float2 c2 = unpack2(acc[i][2]);
        const float2 c3 = unpack2(acc[i][3]);
        const int r0 = row0 + ty * 8 + 2 * i;
        if (r0 < N) {
            __half2 ha = __floats2half2_rn(c0.x + bv.x, c1.x + bv.y);
            __half2 hb = __floats2half2_rn(c2.x + bv.z, c3.x + bv.w);
            __half2* dst = reinterpret_cast<__half2*>(
                               g_h + (size_t)r0 * OUT_FT + tx * 4);
            dst[0] = ha; dst[1] = hb;
        }
        if (r0 + 1 < N) {
            __half2 ha = __floats2half2_rn(c0.y + bv.x, c1.y + bv.y);
            __half2 hb = __floats2half2_rn(c2.y + bv.z, c3.y + bv.w);
            __half2* dst = reinterpret_cast<__half2*>(
                               g_h + (size_t)(r0 + 1) * OUT_FT + tx * 4);
            dst[0] = ha; dst[1] = hb;
        }
    }

    // Fused histogram. Return value = rank of edge within its row.
    const int stride = gridDim.x * 128;
    for (int e = blockIdx.x * 128 + tid; e < E; e += stride) {
        const int rk = atomicAdd(&g_cnt[__ldg(&erow[e])], 1);
        g_rank[e] = (unsigned short)rk;
    }
}

// ---------------------------------------------------------------------------
// K2: shuffle-based block exclusive scan of counts -> g_lex; reset g_cnt;
// block totals -> g_part.
// ---------------------------------------------------------------------------
__global__ __launch_bounds__(256)
void scanB_kernel(int N) {
    __shared__ int ws[8];
    const int tid  = threadIdx.x;
    const int lane = tid & 31;
    const int wid  = tid >> 5;
    const int idx  = blockIdx.x * 256 + tid;

    const int v = (idx < N) ? g_cnt[idx] : 0;
    int inc = v;
    #pragma unroll
    for (int off = 1; off < 32; off <<= 1) {
        const int t = __shfl_up_sync(0xffffffffu, inc, off);
        if (lane >= off) inc += t;
    }
    if (lane == 31) ws[wid] = inc;
    __syncthreads();
    if (wid == 0) {
        int wv = (lane < 8) ? ws[lane] : 0;
        #pragma unroll
        for (int off = 1; off < 8; off <<= 1) {
            const int t = __shfl_up_sync(0xffffffffu, wv, off);
            if (lane >= off) wv += t;
        }
        if (lane < 8) ws[lane] = wv;
    }
    __syncthreads();
    const int wofs = (wid > 0) ? ws[wid - 1] : 0;
    g_lex[idx] = wofs + inc - v;          // exclusive
    if (idx < N) g_cnt[idx] = 0;          // restore invariant
    if (tid == 255) g_part[blockIdx.x] = ws[7];
}

// ---------------------------------------------------------------------------
// K3: single-block (512 thr) shuffle exclusive scan of g_part[0..NB)
// ---------------------------------------------------------------------------
__global__ __launch_bounds__(NB_CAP)
void scanP_kernel(int NB) {
    __shared__ int ws[16];
    const int tid  = threadIdx.x;
    const int lane = tid & 31;
    const int wid  = tid >> 5;

    const int v = (tid < NB) ? g_part[tid] : 0;
    int inc = v;
    #pragma unroll
    for (int off = 1; off < 32; off <<= 1) {
        const int t = __shfl_up_sync(0xffffffffu, inc, off);
        if (lane >= off) inc += t;
    }
    if (lane == 31) ws[wid] = inc;
    __syncthreads();
    if (wid == 0) {
        int wv = (lane < 16) ? ws[lane] : 0;
        #pragma unroll
        for (int off = 1; off < 16; off <<= 1) {
            const int t = __shfl_up_sync(0xffffffffu, wv, off);
            if (lane >= off) wv += t;
        }
        if (lane < 16) ws[lane] = wv;
    }
    __syncthreads();
    const int wofs = (wid > 0) ? ws[wid - 1] : 0;
    if (tid < NB) g_part[tid] = wofs + inc - v;
}

// ---------------------------------------------------------------------------
// K4: scatter edges into CSR (pure permute, no atomics)
// ---------------------------------------------------------------------------
__global__ __launch_bounds__(256)
void scatter_kernel(const int*   __restrict__ erow,
                    const int*   __restrict__ ecol,
                    const float* __restrict__ eval,
                    int E) {
    const int e = blockIdx.x * 256 + threadIdx.x;
    if (e >= E) return;
    const int row = erow[e];
    const int pos = g_lex[row] + g_part[row >> 8] + (int)g_rank[e];
    g_pairs[pos] = make_int2(ecol[e], __float_as_int(eval[e]));
}

// ---------------------------------------------------------------------------
// K5: warp-per-row gather + fused PReLU. Lane owns cols (2*lane, 2*lane+1).
// fp16 h: one 128B L2 line per edge across the warp.
// ---------------------------------------------------------------------------
__global__ __launch_bounds__(256)
void gather_kernel(float* __restrict__ out,
                   const float* __restrict__ alpha,
                   int N) {
    const int lane = threadIdx.x & 31;
    const int row  = blockIdx.x * 8 + (threadIdx.x >> 5);
    if (row >= N) return;

    const int start = g_lex[row]     + g_part[row >> 8];
    const int end   = g_lex[row + 1] + g_part[(row + 1) >> 8];

    float2 acc = make_float2(0.f, 0.f);
    const __half2* __restrict__ hh = reinterpret_cast<const __half2*>(g_h);

    int j = start;
    for (; j + 1 < end; j += 2) {
        const int2 p0 = __ldg(&g_pairs[j]);
        const int2 p1 = __ldg(&g_pairs[j + 1]);
        const float2 a0 = __half22float2(__ldg(&hh[(size_t)p0.x * 32 + lane]));
        const float2 a1 = __half22float2(__ldg(&hh[(size_t)p1.x * 32 + lane]));
        const float v0 = __int_as_float(p0.y);
        const float v1 = __int_as_float(p1.y);
        acc.x = fmaf(v0, a0.x, acc.x);
        acc.y = fmaf(v0, a0.y, acc.y);
        acc.x = fmaf(v1, a1.x, acc.x);
        acc.y = fmaf(v1, a1.y, acc.y);
    }
    if (j < end) {
        const int2 p = __ldg(&g_pairs[j]);
        const float2 a = __half22float2(__ldg(&hh[(size_t)p.x * 32 + lane]));
        const float v = __int_as_float(p.y);
        acc.x = fmaf(v, a.x, acc.x);
        acc.y = fmaf(v, a.y, acc.y);
    }

    const float al = __ldg(alpha);
    acc.x = acc.x >= 0.f ? acc.x : al * acc.x;
    acc.y = acc.y >= 0.f ? acc.y : al * acc.y;
    reinterpret_cast<float2*>(out)[(size_t)row * 32 + lane] = acc;
}

// ---------------------------------------------------------------------------
// Launch. Inputs: x, W, b, alpha, edge_row, edge_col, edge_val
// ---------------------------------------------------------------------------
extern "C" void kernel_launch(void* const* d_in, const int* in_sizes, int n_in,
                              void* d_out, int out_size) {
    const float* x     = (const float*)d_in[0];
    const float* W     = (const float*)d_in[1];
    const float* b     = (const float*)d_in[2];
    const float* alpha = (const float*)d_in[3];
    const int*   erow  = (const int*)  d_in[4];
    const int*   ecol  = (const int*)  d_in[5];
    const float* eval  = (const float*)d_in[6];

    const int N  = in_sizes[0] / IN_FT;
    const int E  = in_sizes[4];
    const int NB = (N + 256) / 256;   // covers idx N; must be <= NB_CAP
    float* out = (float*)d_out;

    gemm_hist_kernel<<<(N + 63) / 64, 128>>>(x, W, b, erow, N, E);
    scanB_kernel<<<NB, 256>>>(N);
    scanP_kernel<<<1, NB_CAP>>>(NB);
    scatter_kernel<<<(E + 255) / 256, 256>>>(erow, ecol, eval, E);
    gather_kernel<<<(N + 7) / 8, 256>>>(out, alpha, N);
}

// round 5
// speedup vs baseline: 1.0683x; 1.0683x over previous
#include <cuda_runtime.h>
#include <cuda_fp16.h>
#include <cstdint>

// ---------------------------------------------------------------------------
// GCN layer on GB300 (sm_103a). Forked-graph pipeline:
//   branch A (main stream): gemm  (h = xW + b, FFMA2 row-pair, fp16 h)
//   branch B (side stream): hist -> scanB -> scanP -> scatter (CSR build)
//   join -> gather (warp = 2 edges/step, fused PReLU)
// ---------------------------------------------------------------------------

#define IN_FT   128
#define OUT_FT  64
#define N_CAP   131072
#define E_CAP   1605632
#define NB_CAP  512

typedef unsigned long long u64;

static __device__ __half         g_h[(size_t)N_CAP * OUT_FT];  // 16.8 MB
static __device__ int            g_cnt[N_CAP + 2];   // zero at entry
static __device__ int            g_lex[N_CAP + 2];   // block-local excl scan
static __device__ int            g_part[NB_CAP];     // block sums -> excl scan
static __device__ unsigned short g_rank[E_CAP];      // edge rank within row
static __device__ int2           g_pairs[E_CAP];     // CSR (col, val bits)

// ---- packed fp32x2 helpers -------------------------------------------------
__device__ __forceinline__ u64 pack2(float lo, float hi) {
    u64 r;
    asm("mov.b64 %0, {%1, %2};" : "=l"(r) : "f"(lo), "f"(hi));
    return r;
}
__device__ __forceinline__ float2 unpack2(u64 v) {
    float2 r;
    asm("mov.b64 {%0, %1}, %2;" : "=f"(r.x), "=f"(r.y) : "l"(v));
    return r;
}
__device__ __forceinline__ u64 fma2(u64 a, u64 b, u64 c) {
    u64 d;
    asm("fma.rn.f32x2 %0, %1, %2, %3;" : "=l"(d) : "l"(a), "l"(b), "l"(c));
    return d;
}

// ---------------------------------------------------------------------------
// A1: GEMM (64-row tile, 128 threads). Xs transposed: Xs[k*64 + row].
// Thread = 4 row-pairs (8 rows) x 4 cols, FFMA2 accumulators.
// ---------------------------------------------------------------------------
__global__ __launch_bounds__(128)
void gemm_kernel(const float* __restrict__ x,
                 const float* __restrict__ W,
                 const float* __restrict__ b,
                 int N) {
    __shared__ float Xs[IN_FT * 64];   // 32 KB, [k][row]

    const int tid  = threadIdx.x;
    const int row0 = blockIdx.x * 64;

    {
        const int r    = tid & 63;
        const int grow = row0 + r;
        const int c4b  = (tid >> 6) * 16;
        const bool ok  = (grow < N);
        const float4* xr = reinterpret_cast<const float4*>(x + (size_t)grow * IN_FT);
        #pragma unroll
        for (int p = 0; p < 16; p++) {
            const int c4 = c4b + p;
            float4 v = make_float4(0.f, 0.f, 0.f, 0.f);
            if (ok) v = xr[c4];
            Xs[(c4 * 4 + 0) * 64 + r] = v.x;
            Xs[(c4 * 4 + 1) * 64 + r] = v.y;
            Xs[(c4 * 4 + 2) * 64 + r] = v.z;
            Xs[(c4 * 4 + 3) * 64 + r] = v.w;
        }
    }
    __syncthreads();

    const int tx = tid & 15;   // cols [4*tx, 4*tx+4)
    const int ty = tid >> 4;   // rows [ty*8, ty*8+8) as 4 pairs

    u64 acc[4][4];
    #pragma unroll
    for (int i = 0; i < 4; i++)
        #pragma unroll
        for (int j = 0; j < 4; j++) acc[i][j] = 0ULL;

    const float4* __restrict__ Wg = reinterpret_cast<const float4*>(W);

    #pragma unroll 4
    for (int k = 0; k < IN_FT; k++) {
        const float4 w = __ldg(&Wg[k * 16 + tx]);
        u64 wd[4];
        wd[0] = pack2(w.x, w.x);
        wd[1] = pack2(w.y, w.y);
        wd[2] = pack2(w.z, w.z);
        wd[3] = pack2(w.w, w.w);

        const u64* xr = reinterpret_cast<const u64*>(&Xs[k * 64 + ty * 8]);
        u64 xp[4];
        xp[0] = xr[0]; xp[1] = xr[1]; xp[2] = xr[2]; xp[3] = xr[3];

        #pragma unroll
        for (int i = 0; i < 4; i++)
            #pragma unroll
            for (int j = 0; j < 4; j++)
                acc[i][j] = fma2(xp[i], wd[j], acc[i][j]);
    }

    const float4 bv = __ldg(reinterpret_cast<const float4*>(b) + tx);
    #pragma unroll
    for (int i = 0; i < 4; i++) {
        const float2 c0 = unpack2(acc[i][0]);
        const float2 c1 = unpack2(acc[i][1]);
        const float2 c2 = unpack2(acc[i][2]);
        const float2 c3 = unpack2(acc[i][3]);
        const int r0 = row0 + ty * 8 + 2 * i;
        if (r0 < N) {
            __half2 ha = __floats2half2_rn(c0.x + bv.x, c1.x + bv.y);
            __half2 hb = __floats2half2_rn(c2.x + bv.z, c3.x + bv.w);
            __half2* dst = reinterpret_cast<__half2*>(
                               g_h + (size_t)r0 * OUT_FT + tx * 4);
            dst[0] = ha; dst[1] = hb;
        }
        if (r0 + 1 < N) {
            __half2 ha = __floats2half2_rn(c0.y + bv.x, c1.y + bv.y);
            __half2 hb = __floats2half2_rn(c2.y + bv.z, c3.y + bv.w);
            __half2* dst = reinterpret_cast<__half2*>(
                               g_h + (size_t)(r0 + 1) * OUT_FT + tx * 4);
            dst[0] = ha; dst[1] = hb;
        }
    }
}

// ---------------------------------------------------------------------------
// B1: histogram with rank. 4 edges per thread, vectorized loads, MLP=4.
// ---------------------------------------------------------------------------
__global__ __launch_bounds__(256)
void hist_kernel(const int* __restrict__ erow, int E) {
    const int idx = blockIdx.x * 256 + threadIdx.x;
    const int e   = idx * 4;
    if (e + 3 < E) {
        const int4 r = __ldg(reinterpret_cast<const int4*>(erow) + idx);
        const int k0 = atomicAdd(&g_cnt[r.x], 1);
        const int k1 = atomicAdd(&g_cnt[r.y], 1);
        const int k2 = atomicAdd(&g_cnt[r.z], 1);
        const int k3 = atomicAdd(&g_cnt[r.w], 1);
        ushort4 rk;
        rk.x = (unsigned short)k0; rk.y = (unsigned short)k1;
        rk.z = (unsigned short)k2; rk.w = (unsigned short)k3;
        *reinterpret_cast<ushort4*>(g_rank + e) = rk;
    } else {
        for (int i = e; i < E; i++)
            g_rank[i] = (unsigned short)atomicAdd(&g_cnt[erow[i]], 1);
    }
}

// ---------------------------------------------------------------------------
// B2: shuffle-based block exclusive scan of counts -> g_lex; reset g_cnt;
// block totals -> g_part.
// ---------------------------------------------------------------------------
__global__ __launch_bounds__(256)
void scanB_kernel(int N) {
    __shared__ int ws[8];
    const int tid  = threadIdx.x;
    const int lane = tid & 31;
    const int wid  = tid >> 5;
    const int idx  = blockIdx.x * 256 + tid;

    const int v = (idx < N) ? g_cnt[idx] : 0;
    int inc = v;
    #pragma unroll
    for (int off = 1; off < 32; off <<= 1) {
        const int t = __shfl_up_sync(0xffffffffu, inc, off);
        if (lane >= off) inc += t;
    }
    if (lane == 31) ws[wid] = inc;
    __syncthreads();
    if (wid == 0) {
        int wv = (lane < 8) ? ws[lane] : 0;
        #pragma unroll
        for (int off = 1; off < 8; off <<= 1) {
            const int t = __shfl_up_sync(0xffffffffu, wv, off);
            if (lane >= off) wv += t;
        }
        if (lane < 8) ws[lane] = wv;
    }
    __syncthreads();
    const int wofs = (wid > 0) ? ws[wid - 1] : 0;
    g_lex[idx] = wofs + inc - v;          // exclusive
    if (idx < N) g_cnt[idx] = 0;          // restore invariant
    if (tid == 255) g_part[blockIdx.x] = ws[7];
}

// ---------------------------------------------------------------------------
// B3: single-block shuffle exclusive scan of g_part[0..NB)
// ---------------------------------------------------------------------------
__global__ __launch_bounds__(NB_CAP)
void scanP_kernel(int NB) {
    __shared__ int ws[16];
    const int tid  = threadIdx.x;
    const int lane = tid & 31;
    const int wid  = tid >> 5;

    const int v = (tid < NB) ? g_part[tid] : 0;
    int inc = v;
    #pragma unroll
    for (int off = 1; off < 32; off <<= 1) {
        const int t = __shfl_up_sync(0xffffffffu, inc, off);
        if (lane >= off) inc += t;
    }
    if (lane == 31) ws[wid] = inc;
    __syncthreads();
    if (wid == 0) {
        int wv = (lane < 16) ? ws[lane] : 0;
        #pragma unroll
        for (int off = 1; off < 16; off <<= 1) {
            const int t = __shfl_up_sync(0xffffffffu, wv, off);
            if (lane >= off) wv += t;
        }
        if (lane < 16) ws[lane] = wv;
    }
    __syncthreads();
    const int wofs = (wid > 0) ? ws[wid - 1] : 0;
    if (tid < NB) g_part[tid] = wofs + inc - v;
}

// ---------------------------------------------------------------------------
// B4: scatter into CSR (no atomics). 4 edges per thread, MLP>=8.
// ---------------------------------------------------------------------------
__global__ __launch_bounds__(256)
void scatter_kernel(const int*   __restrict__ erow,
                    const int*   __restrict__ ecol,
                    const float* __restrict__ eval,
                    int E) {
    const int idx = blockIdx.x * 256 + threadIdx.x;
    const int e   = idx * 4;
    if (e + 3 < E) {
        const int4   r  = __ldg(reinterpret_cast<const int4*>(erow) + idx);
        const int4   c  = __ldg(reinterpret_cast<const int4*>(ecol) + idx);
        const float4 v  = __ldg(reinterpret_cast<const float4*>(eval) + idx);
        const ushort4 rk = *reinterpret_cast<const ushort4*>(g_rank + e);
        const int p0 = g_lex[r.x] + g_part[r.x >> 8] + (int)rk.x;
        const int p1 = g_lex[r.y] + g_part[r.y >> 8] + (int)rk.y;
        const int p2 = g_lex[r.z] + g_part[r.z >> 8] + (int)rk.z;
        const int p3 = g_lex[r.w] + g_part[r.w >> 8] + (int)rk.w;
        g_pairs[p0] = make_int2(c.x, __float_as_int(v.x));
        g_pairs[p1] = make_int2(c.y, __float_as_int(v.y));
        g_pairs[p2] = make_int2(c.z, __float_as_int(v.z));
        g_pairs[p3] = make_int2(c.w, __float_as_int(v.w));
    } else {
        for (int i = e; i < E; i++) {
            const int row = erow[i];
            const int pos = g_lex[row] + g_part[row >> 8] + (int)g_rank[i];
            g_pairs[pos] = make_int2(ecol[i], __float_as_int(eval[i]));
        }
    }
}

// ---------------------------------------------------------------------------
// J1: gather + fused PReLU. Warp = one row; two half-warps process two edges
// per step (fp16 row = 128B = 16 lanes x uint2). Unroll x2 -> 4 edges in
// flight. Final shfl_xor(16) combines the two half-warp accumulators.
// ---------------------------------------------------------------------------
__global__ __launch_bounds__(256)
void gather_kernel(float* __restrict__ out,
                   const float* __restrict__ alpha,
                   int N) {
    const int lane = threadIdx.x & 31;
    const int sub  = lane & 15;    // col group: cols [sub*4, sub*4+4)
    const int half = lane >> 4;    // which edge of the pair
    const int row  = blockIdx.x * 8 + (threadIdx.x >> 5);
    if (row >= N) return;

    const int start = g_lex[row]     + g_part[row >> 8];
    const int end   = g_lex[row + 1] + g_part[(row + 1) >> 8];

    float4 acc = make_float4(0.f, 0.f, 0.f, 0.f);
    const uint2* __restrict__ hh = reinterpret_cast<const uint2*>(g_h);

    int jb = start;
    for (; jb + 3 < end; jb += 4) {
        const int2 p0 = __ldg(&g_pairs[jb + half]);
        const int2 p1 = __ldg(&g_pairs[jb + 2 + half]);
        const uint2 q0 = __ldg(&hh[(size_t)p0.x * 16 + sub]);
        const uint2 q1 = __ldg(&hh[(size_t)p1.x * 16 + sub]);
        const float v0 = __int_as_float(p0.y);
        const float v1 = __int_as_float(p1.y);
        const float2 a0 = __half22float2(*reinterpret_cast<const __half2*>(&q0.x));
        const float2 b0 = __half22float2(*reinterpret_cast<const __half2*>(&q0.y));
        const float2 a1 = __half22float2(*reinterpret_cast<const __half2*>(&q1.x));
        const float2 b1 = __half22float2(*reinterpret_cast<const __half2*>(&q1.y));
        acc.x = fmaf(v0, a0.x, acc.x);
        acc.y = fmaf(v0, a0.y, acc.y);
        acc.z = fmaf(v0, b0.x, acc.z);
        acc.w = fmaf(v0, b0.y, acc.w);
        acc.x = fmaf(v1, a1.x, acc.x);
        acc.y = fmaf(v1, a1.y, acc.y);
        acc.z = fmaf(v1, b1.x, acc.z);
        acc.w = fmaf(v1, b1.y, acc.w);
    }
    for (; jb + half < end; jb += 2) {
        const int2 p = __ldg(&g_pairs[jb + half]);
        const uint2 q = __ldg(&hh[(size_t)p.x * 16 + sub]);
        const float v = __int_as_float(p.y);
        const float2 a = __half22float2(*reinterpret_cast<const __half2*>(&q.x));
        const float2 c = __half22float2(*reinterpret_cast<const __half2*>(&q.y));
        acc.x = fmaf(v, a.x, acc.x);
        acc.y = fmaf(v, a.y, acc.y);
        acc.z = fmaf(v, c.x, acc.z);
        acc.w = fmaf(v, c.y, acc.w);
    }

    // combine the two half-warp partials (same cols, different edges)
    acc.x += __shfl_xor_sync(0xffffffffu, acc.x, 16);
    acc.y += __shfl_xor_sync(0xffffffffu, acc.y, 16);
    acc.z += __shfl_xor_sync(0xffffffffu, acc.z, 16);
    acc.w += __shfl_xor_sync(0xffffffffu, acc.w, 16);

    if (half == 0) {
        const float al = __ldg(alpha);
        acc.x = acc.x >= 0.f ? acc.x : al * acc.x;
        acc.y = acc.y >= 0.f ? acc.y : al * acc.y;
        acc.z = acc.z >= 0.f ? acc.z : al * acc.z;
        acc.w = acc.w >= 0.f ? acc.w : al * acc.w;
        reinterpret_cast<float4*>(out)[(size_t)row * 16 + sub] = acc;
    }
}

// ---------------------------------------------------------------------------
// Launch. Inputs: x, W, b, alpha, edge_row, edge_col, edge_val
// Fork-join: GEMM on the main (capture) stream, CSR build on a side stream.
// ---------------------------------------------------------------------------
extern "C" void kernel_launch(void* const* d_in, const int* in_sizes, int n_in,
                              void* d_out, int out_size) {
    const float* x     = (const float*)d_in[0];
    const float* W     = (const float*)d_in[1];
    const float* b     = (const float*)d_in[2];
    const float* alpha = (const float*)d_in[3];
    const int*   erow  = (const int*)  d_in[4];
    const int*   ecol  = (const int*)  d_in[5];
    const float* eval  = (const float*)d_in[6];

    const int N  = in_sizes[0] / IN_FT;
    const int E  = in_sizes[4];
    const int NB = (N + 256) / 256;   // covers idx N; must be <= NB_CAP
    float* out = (float*)d_out;

    const int EB4 = (E + 1023) / 1024;   // 4 edges/thread, 256 thr/block

    static cudaStream_t s_side = nullptr;
    static cudaEvent_t  ev_fork = nullptr, ev_join = nullptr;
    if (s_side == nullptr) {
        cudaStreamCreateWithFlags(&s_side, cudaStreamNonBlocking);
        cudaEventCreateWithFlags(&ev_fork, cudaEventDisableTiming);
        cudaEventCreateWithFlags(&ev_join, cudaEventDisableTiming);
    }

    if (s_side != nullptr && ev_fork != nullptr && ev_join != nullptr) {
        // fork
        cudaEventRecord(ev_fork, 0);
        cudaStreamWaitEvent(s_side, ev_fork, 0);
        // branch A: GEMM on main stream
        gemm_kernel<<<(N + 63) / 64, 128>>>(x, W, b, N);
        // branch B: CSR build on side stream
        hist_kernel   <<<EB4, 256, 0, s_side>>>(erow, E);
        scanB_kernel  <<<NB, 256, 0, s_side>>>(N);
        scanP_kernel  <<<1, NB_CAP, 0, s_side>>>(NB);
        scatter_kernel<<<EB4, 256, 0, s_side>>>(erow, ecol, eval, E);
        // join
        cudaEventRecord(ev_join, s_side);
        cudaStreamWaitEvent(0, ev_join, 0);
        gather_kernel<<<(N + 7) / 8, 256>>>(out, alpha, N);
    } else {
        // fallback: fully sequential on the main stream
        gemm_kernel   <<<(N + 63) / 64, 128>>>(x, W, b, N);
        hist_kernel   <<<EB4, 256>>>(erow, E);
        scanB_kernel  <<<NB, 256>>>(N);
        scanP_kernel  <<<1, NB_CAP>>>(NB);
        scatter_kernel<<<EB4, 256>>>(erow, ecol, eval, E);
        gather_kernel <<<(N + 7) / 8, 256>>>(out, alpha, N);
    }
}